// round 2
// baseline (speedup 1.0000x reference)
#include <cuda_runtime.h>
#include <cstdint>

// Depthwise 9x9 cross-correlation, stride 1, pad 4, single shared kernel.
// X: (32,64,256,256) fp32 -> out same shape. 2048 independent 256x256 images.
//
// Strategy: fp32 compute via packed fma.rn.f32x2 (SASS FFMA2, 2 FMA per fma-pipe
// issue). Thread owns 2 output columns (one f32x2 accumulator chain) x 8 rows.
// CTA = 256 threads = 32 col-pairs x 8 row-groups -> 64x64 output tile.
// Input tile (72x72 incl. halo) staged in smem; kernel coefficients pre-packed
// {k,k} in smem, then register-resident per u-group of 3 (54 regs) so the inner
// loop is pure FFMA2 with no per-FMA shared loads.

#define IMG_H 256
#define IMG_W 256
#define SPITCH 72
#define TILE 64

__device__ __forceinline__ unsigned long long pack2(float lo, float hi) {
    unsigned long long r;
    asm("mov.b64 %0, {%1, %2};" : "=l"(r) : "f"(lo), "f"(hi));
    return r;
}

__device__ __forceinline__ void ffma2(unsigned long long& d,
                                      unsigned long long a,
                                      unsigned long long b) {
    // d = a * b + d, elementwise on packed f32x2
    asm("fma.rn.f32x2 %0, %1, %2, %0;" : "+l"(d) : "l"(a), "l"(b));
}

__global__ __launch_bounds__(256, 2)
void conv9x9_kernel(const float* __restrict__ X,
                    const float* __restrict__ Kf,
                    float* __restrict__ out) {
    __shared__ float xs[SPITCH * SPITCH];
    __shared__ unsigned long long k2s[81];

    const int bx   = blockIdx.x;
    const int img  = bx >> 4;         // 2048 images
    const int tile = bx & 15;         // 4x4 tiles of 64x64
    const int row0 = (tile >> 2) * TILE;
    const int col0 = (tile & 3) * TILE;

    const float* __restrict__ Xi = X + (size_t)img * (IMG_H * IMG_W);
    const int tid = threadIdx.x;

    // Pre-pack kernel coefficients as {k,k} for f32x2 broadcast-multiply.
    if (tid < 81) {
        float kv = Kf[tid];
        k2s[tid] = pack2(kv, kv);
    }

    // Stage input tile (with 4-halo on all sides) into smem, zero-padded.
    #pragma unroll 4
    for (int idx = tid; idx < SPITCH * SPITCH; idx += 256) {
        int r = idx / SPITCH;
        int c = idx - r * SPITCH;
        int gr = row0 - 4 + r;
        int gc = col0 - 4 + c;
        float v = 0.0f;
        if ((unsigned)gr < IMG_H && (unsigned)gc < IMG_W)
            v = Xi[gr * IMG_W + gc];
        xs[idx] = v;
    }
    __syncthreads();

    const int cg = tid & 31;   // column-pair index: output cols 2*cg, 2*cg+1
    const int rg = tid >> 5;   // row group: output rows rg*8 .. rg*8+7
    const int cbase = 2 * cg;

    unsigned long long acc[8] = {0ull,0ull,0ull,0ull,0ull,0ull,0ull,0ull};

    // u split into 3 groups of 3 so the packed k coefficients fit in registers
    // (27 x 64b = 54 regs) -> no shared loads in the FMA inner loop.
    #pragma unroll
    for (int g = 0; g < 3; ++g) {
        unsigned long long k2r[27];
        #pragma unroll
        for (int j = 0; j < 27; ++j) k2r[j] = k2s[g * 27 + j];

        // Input rows needed by this u-group: t = o + u, o in [0,8), u in [3g,3g+3)
        #pragma unroll
        for (int tt = 0; tt < 10; ++tt) {
            const int t = 3 * g + tt;
            const float2* wr =
                (const float2*)&xs[(rg * 8 + t) * SPITCH + cbase];
            float2 a0 = wr[0], a1 = wr[1], a2 = wr[2], a3 = wr[3], a4 = wr[4];

            // 9 shifted packed windows covering horizontal taps v = 0..8
            unsigned long long P[9];
            P[0] = pack2(a0.x, a0.y);
            P[2] = pack2(a1.x, a1.y);
            P[4] = pack2(a2.x, a2.y);
            P[6] = pack2(a3.x, a3.y);
            P[8] = pack2(a4.x, a4.y);
            P[1] = pack2(a0.y, a1.x);
            P[3] = pack2(a1.y, a2.x);
            P[5] = pack2(a2.y, a3.x);
            P[7] = pack2(a3.y, a4.x);

            #pragma unroll
            for (int v = 0; v < 9; ++v) {
                #pragma unroll
                for (int uu = 0; uu < 3; ++uu) {
                    const int o = tt - uu;      // = t - u, output row in chain
                    if (o >= 0 && o < 8)
                        ffma2(acc[o], P[v], k2r[uu * 9 + v]);
                }
            }
        }
    }

    float* __restrict__ Oi = out + (size_t)img * (IMG_H * IMG_W);
    #pragma unroll
    for (int o = 0; o < 8; ++o) {
        float lo, hi;
        asm("mov.b64 {%0, %1}, %2;" : "=f"(lo), "=f"(hi) : "l"(acc[o]));
        *(float2*)&Oi[(row0 + rg * 8 + o) * IMG_W + col0 + cbase] =
            make_float2(lo, hi);
    }
}

extern "C" void kernel_launch(void* const* d_in, const int* in_sizes, int n_in,
                              void* d_out, int out_size) {
    const float* X = (const float*)d_in[0];
    const float* K = (const float*)d_in[1];
    // Safety: metadata order should be X (134217728) then K (81).
    if (n_in >= 2 && in_sizes[0] == 81) {
        const float* t = X; X = K; K = t;
    }
    conv9x9_kernel<<<32768, 256>>>(X, K, (float*)d_out);
}

// round 3
// speedup vs baseline: 1.1271x; 1.1271x over previous
#include <cuda_runtime.h>
#include <cstdint>

// Depthwise 9x9 conv, stride 1, pad 4. X:(32,64,256,256) fp32, one shared kernel.
// R2: all-FFMA2 inner loop with ZERO packing MOVs.
//  - smem holds two copies of the input tile: xe (aligned) and xof (shifted by
//    one float, 8B-aligned base) -> every horizontal window (any parity) is a
//    direct ld.shared.b64 into a register pair.
//  - v-split (3 groups of 3 horizontal taps): 27 packed k coeffs (54 regs)
//    register-resident per group; every input row loaded once per group with
//    only 5 pack loads serving TWO column chains (4 output cols/thread).
//  - thread = 4 cols x 8 rows; CTA 256 threads = 16 colgroups x 16 rowgroups
//    -> 64 x 128 output tile. 1296 FFMA2 + 240 pack-LDS per thread.

#define IMG 256
#define XE_STRIDE 72
#define XO_STRIDE 70
#define ROWS_SM 136                       // 128 + 8 halo
#define XE_FLOATS (ROWS_SM * XE_STRIDE)   // 9792
#define XO_FLOATS (ROWS_SM * XO_STRIDE)   // 9520
#define SMEM_BYTES ((XE_FLOATS + XO_FLOATS) * 4 + 81 * 8)

__device__ __forceinline__ unsigned long long pack2(float lo, float hi) {
    unsigned long long r;
    asm("mov.b64 %0, {%1, %2};" : "=l"(r) : "f"(lo), "f"(hi));
    return r;
}

__device__ __forceinline__ void ffma2(unsigned long long& d,
                                      unsigned long long a,
                                      unsigned long long b) {
    asm("fma.rn.f32x2 %0, %1, %2, %0;" : "+l"(d) : "l"(a), "l"(b));
}

__global__ __launch_bounds__(256, 2)
void conv9x9_kernel(const float* __restrict__ X,
                    const float* __restrict__ Kf,
                    float* __restrict__ out) {
    extern __shared__ float smem[];
    float* xe  = smem;
    float* xof = smem + XE_FLOATS;                 // rows shifted by one float
    unsigned long long* k2s =
        (unsigned long long*)(smem + XE_FLOATS + XO_FLOATS);

    const int bx   = blockIdx.x;
    const int img  = bx >> 3;                      // 2048 images
    const int t6   = bx & 7;                       // 4 col-tiles x 2 row-tiles
    const int row0 = (t6 >> 2) * 128;
    const int col0 = (t6 & 3) * 64;

    const float* __restrict__ Xi = X + (size_t)img * (IMG * IMG);
    const int tid = threadIdx.x;

    if (tid < 81) {
        float kv = Kf[tid];
        k2s[tid] = pack2(kv, kv);
    }

    // Stage tile (4-halo, zero-padded) into both copies.
    #pragma unroll 4
    for (int idx = tid; idx < XE_FLOATS; idx += 256) {
        int r  = idx / XE_STRIDE;
        int c  = idx - r * XE_STRIDE;
        int gr = row0 - 4 + r;
        int gc = col0 - 4 + c;
        float v = 0.0f;
        if ((unsigned)gr < IMG && (unsigned)gc < IMG)
            v = Xi[gr * IMG + gc];
        xe[idx] = v;
        if (c >= 1 && c <= 70)
            xof[r * XO_STRIDE + (c - 1)] = v;      // shifted copy
    }
    __syncthreads();

    const int cg    = tid & 15;     // 16 colgroups -> output cols 4*cg..4*cg+3
    const int rg    = tid >> 4;     // 16 rowgroups -> output rows 8*rg..8*rg+7
    const int jb    = cg * 4;       // chain A cols (jb, jb+1), B (jb+2, jb+3)
    const int rbase = rg * 8;

    unsigned long long accA[8] = {0ull,0ull,0ull,0ull,0ull,0ull,0ull,0ull};
    unsigned long long accB[8] = {0ull,0ull,0ull,0ull,0ull,0ull,0ull,0ull};

    #pragma unroll
    for (int g = 0; g < 3; ++g) {
        // Register-resident packed coefficients for taps v = 3g..3g+2.
        unsigned long long kr[27];
        #pragma unroll
        for (int u = 0; u < 9; ++u)
            #pragma unroll
            for (int vv = 0; vv < 3; ++vv)
                kr[u * 3 + vv] = k2s[u * 9 + g * 3 + vv];

        #pragma unroll
        for (int t = 0; t < 16; ++t) {
            const float* er = &xe [(rbase + t) * XE_STRIDE];
            const float* od = &xof[(rbase + t) * XO_STRIDE];

            // Packs P[m] = input cols (jb+3g+m, jb+3g+m+1); direct 64b loads.
            unsigned long long P[5];
            #pragma unroll
            for (int m = 0; m < 5; ++m) {
                const int s = g * 3 + m;           // jb even -> parity = s&1
                if ((s & 1) == 0)
                    P[m] = *(const unsigned long long*)&er[jb + s];
                else
                    P[m] = *(const unsigned long long*)&od[jb + s - 1];
            }

            // Chain A uses P[0..2], chain B uses P[2..4]; k shared.
            #pragma unroll
            for (int vv = 0; vv < 3; ++vv) {
                #pragma unroll
                for (int u = 0; u < 9; ++u) {
                    const int o = t - u;           // output row in chain
                    if (o >= 0 && o < 8) {
                        ffma2(accA[o], P[vv],     kr[u * 3 + vv]);
                        ffma2(accB[o], P[vv + 2], kr[u * 3 + vv]);
                    }
                }
            }
        }
    }

    float* __restrict__ Oi = out + (size_t)img * (IMG * IMG);
    #pragma unroll
    for (int o = 0; o < 8; ++o) {
        float ax, ay, bx2, by;
        asm("mov.b64 {%0, %1}, %2;" : "=f"(ax), "=f"(ay)  : "l"(accA[o]));
        asm("mov.b64 {%0, %1}, %2;" : "=f"(bx2), "=f"(by) : "l"(accB[o]));
        *(float4*)&Oi[(size_t)(row0 + rbase + o) * IMG + col0 + jb] =
            make_float4(ax, ay, bx2, by);
    }
}

extern "C" void kernel_launch(void* const* d_in, const int* in_sizes, int n_in,
                              void* d_out, int out_size) {
    const float* X = (const float*)d_in[0];
    const float* K = (const float*)d_in[1];
    if (n_in >= 2 && in_sizes[0] == 81) {          // metadata-order safety
        const float* t = X; X = K; K = t;
    }
    cudaFuncSetAttribute(conv9x9_kernel,
                         cudaFuncAttributeMaxDynamicSharedMemorySize,
                         SMEM_BYTES);
    conv9x9_kernel<<<16384, 256, SMEM_BYTES>>>(X, K, (float*)d_out);
}

// round 4
// speedup vs baseline: 1.1686x; 1.0368x over previous
#include <cuda_runtime.h>
#include <cstdint>

// Depthwise 9x9 conv, stride 1, pad 4. X:(32,64,256,256) fp32, one shared kernel.
// R3: conflict-free LDS + deeper row blocking.
//  - thread = 2 cols (one f32x2 chain) x 16 rows. Warp lanes are 32 contiguous
//    column-pairs -> every LDS.64 is a contiguous 256B access: 2 wavefronts,
//    zero bank conflicts.
//  - dual shifted smem copies (xe aligned, xof shifted one float, both
//    stride 72 so all row bases are 8B-aligned) -> any window parity is one
//    direct ld.shared.b64, no packing MOVs.
//  - v-split in 3 groups of 3 taps; 27 packed {k,k} coeffs register-resident
//    per group. Per thread: 1296 FFMA2, 216 pack-LDS, 81 k-LDS (4.4:1).
//  - CTA 256 thr = 32 colpairs x 8 rowgroups -> 64x128 tile; grid 16384.

#define IMG 256
#define SST 72                            // stride for BOTH smem copies
#define ROWS_SM 136                       // 128 + 8 halo
#define COPY_FLOATS (ROWS_SM * SST)       // 9792
#define SMEM_BYTES (2 * COPY_FLOATS * 4 + 81 * 8)

__device__ __forceinline__ unsigned long long pack2(float lo, float hi) {
    unsigned long long r;
    asm("mov.b64 %0, {%1, %2};" : "=l"(r) : "f"(lo), "f"(hi));
    return r;
}

__device__ __forceinline__ void ffma2(unsigned long long& d,
                                      unsigned long long a,
                                      unsigned long long b) {
    asm("fma.rn.f32x2 %0, %1, %2, %0;" : "+l"(d) : "l"(a), "l"(b));
}

__global__ __launch_bounds__(256, 2)
void conv9x9_kernel(const float* __restrict__ X,
                    const float* __restrict__ Kf,
                    float* __restrict__ out) {
    extern __shared__ float smem[];
    float* xe  = smem;                       // aligned copy
    float* xof = smem + COPY_FLOATS;         // shifted-by-one copy
    unsigned long long* k2s =
        (unsigned long long*)(smem + 2 * COPY_FLOATS);

    const int bx   = blockIdx.x;
    const int img  = bx >> 3;                // 2048 images
    const int t6   = bx & 7;                 // 4 col-tiles x 2 row-tiles
    const int row0 = (t6 >> 2) * 128;
    const int col0 = (t6 & 3) * 64;

    const float* __restrict__ Xi = X + (size_t)img * (IMG * IMG);
    const int tid = threadIdx.x;

    if (tid < 81) {
        float kv = Kf[tid];
        k2s[tid] = pack2(kv, kv);
    }

    // Stage input tile (4-halo, zero-padded) into both copies.
    #pragma unroll 4
    for (int idx = tid; idx < COPY_FLOATS; idx += 256) {
        int r  = idx / SST;
        int c  = idx - r * SST;
        int gr = row0 - 4 + r;
        int gc = col0 - 4 + c;
        float v = 0.0f;
        if ((unsigned)gr < IMG && (unsigned)gc < IMG)
            v = Xi[gr * IMG + gc];
        xe[idx] = v;
        if (c >= 1)
            xof[r * SST + (c - 1)] = v;      // shifted copy, cols 0..70
    }
    __syncthreads();

    const int cg    = tid & 31;              // 32 colpairs: cols 2cg, 2cg+1
    const int rg    = tid >> 5;              // 8 rowgroups x 16 rows
    const int jb    = 2 * cg;                // even
    const int rbase = rg * 16;

    unsigned long long acc[16];
    #pragma unroll
    for (int i = 0; i < 16; ++i) acc[i] = 0ull;

    #pragma unroll
    for (int g = 0; g < 3; ++g) {
        // Register-resident packed coefficients for taps v = 3g..3g+2.
        unsigned long long kr[27];
        #pragma unroll
        for (int u = 0; u < 9; ++u)
            #pragma unroll
            for (int vv = 0; vv < 3; ++vv)
                kr[u * 3 + vv] = k2s[u * 9 + g * 3 + vv];

        #pragma unroll
        for (int t = 0; t < 24; ++t) {
            const float* er = &xe [(rbase + t) * SST];
            const float* od = &xof[(rbase + t) * SST];

            // P[m] = packed input cols (jb+3g+m, jb+3g+m+1), one LDS.64 each.
            unsigned long long P[3];
            #pragma unroll
            for (int m = 0; m < 3; ++m) {
                const int s = g * 3 + m;
                if ((s & 1) == 0)
                    P[m] = *(const unsigned long long*)&er[jb + s];
                else
                    P[m] = *(const unsigned long long*)&od[jb + s - 1];
            }

            #pragma unroll
            for (int vv = 0; vv < 3; ++vv) {
                #pragma unroll
                for (int u = 0; u < 9; ++u) {
                    const int o = t - u;            // output row in chain
                    if (o >= 0 && o < 16)
                        ffma2(acc[o], P[vv], kr[u * 3 + vv]);
                }
            }
        }
    }

    float* __restrict__ Oi = out + (size_t)img * (IMG * IMG);
    #pragma unroll
    for (int o = 0; o < 16; ++o) {
        float lo, hi;
        asm("mov.b64 {%0, %1}, %2;" : "=f"(lo), "=f"(hi) : "l"(acc[o]));
        *(float2*)&Oi[(size_t)(row0 + rbase + o) * IMG + col0 + jb] =
            make_float2(lo, hi);
    }
}

extern "C" void kernel_launch(void* const* d_in, const int* in_sizes, int n_in,
                              void* d_out, int out_size) {
    const float* X = (const float*)d_in[0];
    const float* K = (const float*)d_in[1];
    if (n_in >= 2 && in_sizes[0] == 81) {    // metadata-order safety
        const float* t = X; X = K; K = t;
    }
    cudaFuncSetAttribute(conv9x9_kernel,
                         cudaFuncAttributeMaxDynamicSharedMemorySize,
                         SMEM_BYTES);
    conv9x9_kernel<<<16384, 256, SMEM_BYTES>>>(X, K, (float*)d_out);
}

// round 5
// speedup vs baseline: 1.3273x; 1.1358x over previous
#include <cuda_runtime.h>
#include <cstdint>

// Depthwise 9x9 conv, stride 1, pad 4. X:(32,64,256,256) fp32, one shared kernel.
// R4: occupancy-focused. 3 CTAs/SM (24 warps) by cutting regs to ~80:
//  - thread = 2 cols x 8 rows (16 acc regs), CTA 256 = 32 colpairs x 8 rowgrps
//    -> 64x64 tile; smem = dual shifted copies of 72x72 (42KB) -> 3 CTAs fit.
//  - k coeffs register-resident in groups of 2 v-taps (36 regs); total LDS is
//    invariant under v-grouping so this is free.
//  - dual shifted smem copies: any window parity is one ld.shared.b64, no MOVs.
//  - inner order (vv outer, u inner): 9 consecutive FFMA2 share P operand ->
//    operand reuse cache keeps RF-bank rt at 2.

#define IMG 256
#define SST 72                            // stride for BOTH smem copies
#define ROWS_SM 72                        // 64 + 8 halo
#define COPY_FLOATS (ROWS_SM * SST)       // 5184
#define SMEM_BYTES (2 * COPY_FLOATS * 4 + 81 * 8)

__device__ __forceinline__ unsigned long long pack2(float lo, float hi) {
    unsigned long long r;
    asm("mov.b64 %0, {%1, %2};" : "=l"(r) : "f"(lo), "f"(hi));
    return r;
}

__device__ __forceinline__ void ffma2(unsigned long long& d,
                                      unsigned long long a,
                                      unsigned long long b) {
    asm("fma.rn.f32x2 %0, %1, %2, %0;" : "+l"(d) : "l"(a), "l"(b));
}

__global__ __launch_bounds__(256, 3)
void conv9x9_kernel(const float* __restrict__ X,
                    const float* __restrict__ Kf,
                    float* __restrict__ out) {
    extern __shared__ float smem[];
    float* xe  = smem;                       // aligned copy
    float* xof = smem + COPY_FLOATS;         // shifted-by-one copy
    unsigned long long* k2s =
        (unsigned long long*)(smem + 2 * COPY_FLOATS);

    const int bx   = blockIdx.x;
    const int img  = bx >> 4;                // 2048 images
    const int t16  = bx & 15;                // 4x4 tiles of 64x64
    const int row0 = (t16 >> 2) * 64;
    const int col0 = (t16 & 3) * 64;

    const float* __restrict__ Xi = X + (size_t)img * (IMG * IMG);
    const int tid = threadIdx.x;

    if (tid < 81) {
        float kv = Kf[tid];
        k2s[tid] = pack2(kv, kv);
    }

    // Stage input tile (4-halo, zero-padded) into both copies.
    #pragma unroll 4
    for (int idx = tid; idx < COPY_FLOATS; idx += 256) {
        int r  = idx / SST;
        int c  = idx - r * SST;
        int gr = row0 - 4 + r;
        int gc = col0 - 4 + c;
        float v = 0.0f;
        if ((unsigned)gr < IMG && (unsigned)gc < IMG)
            v = Xi[gr * IMG + gc];
        xe[idx] = v;
        if (c >= 1)
            xof[r * SST + (c - 1)] = v;      // shifted copy, cols 0..70
    }
    __syncthreads();

    const int cg    = tid & 31;              // 32 colpairs: cols 2cg, 2cg+1
    const int rg    = tid >> 5;              // 8 rowgroups x 8 rows
    const int jb    = 2 * cg;                // even
    const int rbase = rg * 8;

    unsigned long long acc[8] = {0ull,0ull,0ull,0ull,0ull,0ull,0ull,0ull};

    // v-taps in 5 groups: {0,1},{2,3},{4,5},{6,7},{8}
    #pragma unroll
    for (int g = 0; g < 5; ++g) {
        const int nv = (g == 4) ? 1 : 2;

        // Register-resident packed coefficients for this v-group (<=36 regs).
        unsigned long long kr[18];
        #pragma unroll
        for (int u = 0; u < 9; ++u)
            #pragma unroll 2
            for (int vv = 0; vv < nv; ++vv)
                kr[u * 2 + vv] = k2s[u * 9 + g * 2 + vv];

        #pragma unroll
        for (int t = 0; t < 16; ++t) {       // input rows rbase..rbase+15
            const float* er = &xe [(rbase + t) * SST];
            const float* od = &xof[(rbase + t) * SST];

            unsigned long long P[2];
            #pragma unroll 2
            for (int vv = 0; vv < nv; ++vv) {
                const int s = g * 2 + vv;    // window shift; jb even
                if ((s & 1) == 0)
                    P[vv] = *(const unsigned long long*)&er[jb + s];
                else
                    P[vv] = *(const unsigned long long*)&od[jb + s - 1];
            }

            #pragma unroll 2
            for (int vv = 0; vv < nv; ++vv) {
                #pragma unroll
                for (int u = 0; u < 9; ++u) {
                    const int o = t - u;     // output row in chain
                    if (o >= 0 && o < 8)
                        ffma2(acc[o], P[vv], kr[u * 2 + vv]);
                }
            }
        }
    }

    float* __restrict__ Oi = out + (size_t)img * (IMG * IMG);
    #pragma unroll
    for (int o = 0; o < 8; ++o) {
        float lo, hi;
        asm("mov.b64 {%0, %1}, %2;" : "=f"(lo), "=f"(hi) : "l"(acc[o]));
        *(float2*)&Oi[(size_t)(row0 + rbase + o) * IMG + col0 + jb] =
            make_float2(lo, hi);
    }
}

extern "C" void kernel_launch(void* const* d_in, const int* in_sizes, int n_in,
                              void* d_out, int out_size) {
    const float* X = (const float*)d_in[0];
    const float* K = (const float*)d_in[1];
    if (n_in >= 2 && in_sizes[0] == 81) {    // metadata-order safety
        const float* t = X; X = K; K = t;
    }
    cudaFuncSetAttribute(conv9x9_kernel,
                         cudaFuncAttributeMaxDynamicSharedMemorySize,
                         SMEM_BYTES);
    conv9x9_kernel<<<32768, 256, SMEM_BYTES>>>(X, K, (float*)d_out);
}

// round 6
// speedup vs baseline: 1.4646x; 1.1035x over previous
#include <cuda_runtime.h>
#include <cstdint>

// Depthwise 9x9 conv, stride 1, pad 4. X:(32,64,256,256) fp32, one shared kernel.
// R5: long chains + small CTAs to beat the crossbar co-limit.
//  - thread = 2 cols x 16 rows (C=16): FFMA2:pack-LDS = 6:1 (was 4.5:1).
//  - CTA = 128 thr = 32 colpairs x 4 rowgroups -> 64x64 tile; dual shifted
//    smem copies (xe stride 72, xof stride 70) = 40.6KB -> 5 CTAs/SM, 20 warps.
//  - single-v k groups: 9 groups, kr = 9 packed {k,k} coeffs (18 regs);
//    inner loop = 1 LDS.64 + 9 FFMA2, acc-reuse distance 9 instrs.
//  - zero packing MOVs (dual-copy handles both window parities), zero bank
//    conflicts (warp-contiguous 8B/lane loads).

#define IMG 256
#define SE 72                              // xe stride (floats)
#define SO 70                              // xof stride (floats)
#define ROWS_SM 72                         // 64 + 8 halo
#define XE_FLOATS (ROWS_SM * SE)           // 5184
#define XO_FLOATS (ROWS_SM * SO)           // 5040
#define SMEM_BYTES ((XE_FLOATS + XO_FLOATS) * 4 + 81 * 8)

__device__ __forceinline__ unsigned long long pack2(float lo, float hi) {
    unsigned long long r;
    asm("mov.b64 %0, {%1, %2};" : "=l"(r) : "f"(lo), "f"(hi));
    return r;
}

__device__ __forceinline__ void ffma2(unsigned long long& d,
                                      unsigned long long a,
                                      unsigned long long b) {
    asm("fma.rn.f32x2 %0, %1, %2, %0;" : "+l"(d) : "l"(a), "l"(b));
}

__global__ __launch_bounds__(128, 5)
void conv9x9_kernel(const float* __restrict__ X,
                    const float* __restrict__ Kf,
                    float* __restrict__ out) {
    extern __shared__ float smem[];
    float* xe  = smem;                     // aligned copy
    float* xof = smem + XE_FLOATS;         // shifted-by-one copy (stride 70)
    unsigned long long* k2s =
        (unsigned long long*)(smem + XE_FLOATS + XO_FLOATS);

    const int bx   = blockIdx.x;
    const int img  = bx >> 4;              // 2048 images
    const int t16  = bx & 15;              // 4x4 tiles of 64x64
    const int row0 = (t16 >> 2) * 64;
    const int col0 = (t16 & 3) * 64;

    const float* __restrict__ Xi = X + (size_t)img * (IMG * IMG);
    const int tid = threadIdx.x;

    if (tid < 81) {
        float kv = Kf[tid];
        k2s[tid] = pack2(kv, kv);
    }

    // Stage tile (4-halo, zero-padded) into both copies.
    #pragma unroll 4
    for (int idx = tid; idx < XE_FLOATS; idx += 128) {
        int r  = idx / SE;
        int c  = idx - r * SE;
        int gr = row0 - 4 + r;
        int gc = col0 - 4 + c;
        float v = 0.0f;
        if ((unsigned)gr < IMG && (unsigned)gc < IMG)
            v = Xi[gr * IMG + gc];
        xe[idx] = v;
        if (c >= 1 && c <= SO)
            xof[r * SO + (c - 1)] = v;     // shifted copy, orig cols 1..70
    }
    __syncthreads();

    const int cg    = tid & 31;            // 32 colpairs: cols 2cg, 2cg+1
    const int rg    = tid >> 5;            // 4 rowgroups x 16 rows
    const int jb    = 2 * cg;              // even
    const int rbase = rg * 16;

    unsigned long long acc[16];
    #pragma unroll
    for (int i = 0; i < 16; ++i) acc[i] = 0ull;

    // One horizontal tap v per group: kr = 9 packed coeffs (u = 0..8).
    #pragma unroll
    for (int g = 0; g < 9; ++g) {
        unsigned long long kr[9];
        #pragma unroll
        for (int u = 0; u < 9; ++u)
            kr[u] = k2s[u * 9 + g];

        // Base pointer for this tap's packed window (parity-resolved once).
        const float* base;
        int stride;
        if ((g & 1) == 0) { base = &xe [rbase * SE + jb + g];     stride = SE; }
        else              { base = &xof[rbase * SO + jb + g - 1]; stride = SO; }

        #pragma unroll
        for (int t = 0; t < 24; ++t) {     // input rows rbase..rbase+23
            unsigned long long P =
                *(const unsigned long long*)(base + t * stride);
            #pragma unroll
            for (int u = 0; u < 9; ++u) {
                const int o = t - u;       // output row in chain
                if (o >= 0 && o < 16)
                    ffma2(acc[o], P, kr[u]);
            }
        }
    }

    float* __restrict__ Oi = out + (size_t)img * (IMG * IMG);
    #pragma unroll
    for (int o = 0; o < 16; ++o) {
        float lo, hi;
        asm("mov.b64 {%0, %1}, %2;" : "=f"(lo), "=f"(hi) : "l"(acc[o]));
        *(float2*)&Oi[(size_t)(row0 + rbase + o) * IMG + col0 + jb] =
            make_float2(lo, hi);
    }
}

extern "C" void kernel_launch(void* const* d_in, const int* in_sizes, int n_in,
                              void* d_out, int out_size) {
    const float* X = (const float*)d_in[0];
    const float* K = (const float*)d_in[1];
    if (n_in >= 2 && in_sizes[0] == 81) {  // metadata-order safety
        const float* t = X; X = K; K = t;
    }
    cudaFuncSetAttribute(conv9x9_kernel,
                         cudaFuncAttributeMaxDynamicSharedMemorySize,
                         SMEM_BYTES);
    conv9x9_kernel<<<32768, 128, SMEM_BYTES>>>(X, K, (float*)d_out);
}

// round 7
// speedup vs baseline: 1.8555x; 1.2669x over previous
#include <cuda_runtime.h>
#include <cstdint>

// Depthwise 9x9 conv, stride 1, pad 4. X:(32,64,256,256) fp32, one shared kernel.
// R6: stall-focused. Same tiling as R5 (128thr CTA, 2col x 16row threads,
// 64x64 tile, dual shifted smem copies, 5 CTAs/SM) plus:
//  - explicit 2-deep software pipeline: P[t+1] loads before row-t FFMA2s
//    -> LDS latency (29cy) covered by >=18 issue-cycles of math.
//  - runtime tap loop (g): ~4KB body fits L0 I$; t/u stay unrolled for
//    compile-time acc[] indexing. Both copies stride 72 -> immediate offsets.
//  - kernel coeffs in __constant__ (LDC, constant port) -> 81 broadcast
//    wavefronts/warp off the shared crossbar.

#define IMG 256
#define SST 72                             // stride for BOTH smem copies
#define ROWS_SM 72                         // 64 + 8 halo
#define COPY_FLOATS (ROWS_SM * SST)        // 5184
#define SMEM_BYTES (2 * COPY_FLOATS * 4)

__constant__ float cK[81];

__device__ __forceinline__ unsigned long long pack2(float lo, float hi) {
    unsigned long long r;
    asm("mov.b64 %0, {%1, %2};" : "=l"(r) : "f"(lo), "f"(hi));
    return r;
}

__device__ __forceinline__ void ffma2(unsigned long long& d,
                                      unsigned long long a,
                                      unsigned long long b) {
    asm("fma.rn.f32x2 %0, %1, %2, %0;" : "+l"(d) : "l"(a), "l"(b));
}

__global__ __launch_bounds__(128, 5)
void conv9x9_kernel(const float* __restrict__ X,
                    float* __restrict__ out) {
    extern __shared__ float smem[];
    float* xe  = smem;                     // aligned copy
    float* xof = smem + COPY_FLOATS;       // shifted-by-one copy (stride 72)

    const int bx   = blockIdx.x;
    const int img  = bx >> 4;              // 2048 images
    const int t16  = bx & 15;              // 4x4 tiles of 64x64
    const int row0 = (t16 >> 2) * 64;
    const int col0 = (t16 & 3) * 64;

    const float* __restrict__ Xi = X + (size_t)img * (IMG * IMG);
    const int tid = threadIdx.x;

    // Stage tile (4-halo, zero-padded) into both copies.
    #pragma unroll 4
    for (int idx = tid; idx < COPY_FLOATS; idx += 128) {
        int r  = idx / SST;
        int c  = idx - r * SST;
        int gr = row0 - 4 + r;
        int gc = col0 - 4 + c;
        float v = 0.0f;
        if ((unsigned)gr < IMG && (unsigned)gc < IMG)
            v = Xi[gr * IMG + gc];
        xe[idx] = v;
        if (c >= 1 && c <= 71)
            xof[r * SST + (c - 1)] = v;    // orig cols 1..71 -> xof 0..70
    }
    __syncthreads();

    const int cg    = tid & 31;            // 32 colpairs: cols 2cg, 2cg+1
    const int rg    = tid >> 5;            // 4 rowgroups x 16 rows
    const int jb    = 2 * cg;              // even
    const int rbase = rg * 16;

    unsigned long long acc[16];
    #pragma unroll
    for (int i = 0; i < 16; ++i) acc[i] = 0ull;

    // Runtime loop over the 9 horizontal taps; small body, L0-resident.
    #pragma unroll 1
    for (int g = 0; g < 9; ++g) {
        // Packed {k,k} coefficients for this tap (LDC, off the crossbar).
        unsigned long long kr[9];
        #pragma unroll
        for (int u = 0; u < 9; ++u) {
            float kv = cK[u * 9 + g];
            kr[u] = pack2(kv, kv);
        }

        // Parity-resolved base for this tap's packed window.
        const float* base = (g & 1) ? &xof[rbase * SST + jb + g - 1]
                                    : &xe [rbase * SST + jb + g];

        // Software pipeline: load row t+1 before computing row t.
        unsigned long long Pc =
            *(const unsigned long long*)(base);
        #pragma unroll
        for (int t = 0; t < 24; ++t) {
            unsigned long long Pn = 0ull;
            if (t < 23)
                Pn = *(const unsigned long long*)(base + (t + 1) * SST);
            #pragma unroll
            for (int u = 0; u < 9; ++u) {
                const int o = t - u;       // output row in chain
                if (o >= 0 && o < 16)
                    ffma2(acc[o], Pc, kr[u]);
            }
            Pc = Pn;
        }
    }

    float* __restrict__ Oi = out + (size_t)img * (IMG * IMG);
    #pragma unroll
    for (int o = 0; o < 16; ++o) {
        float lo, hi;
        asm("mov.b64 {%0, %1}, %2;" : "=f"(lo), "=f"(hi) : "l"(acc[o]));
        *(float2*)&Oi[(size_t)(row0 + rbase + o) * IMG + col0 + jb] =
            make_float2(lo, hi);
    }
}

extern "C" void kernel_launch(void* const* d_in, const int* in_sizes, int n_in,
                              void* d_out, int out_size) {
    const float* X = (const float*)d_in[0];
    const float* K = (const float*)d_in[1];
    if (n_in >= 2 && in_sizes[0] == 81) {  // metadata-order safety
        const float* t = X; X = K; K = t;
    }
    cudaMemcpyToSymbolAsync(cK, K, 81 * sizeof(float), 0,
                            cudaMemcpyDeviceToDevice, 0);
    cudaFuncSetAttribute(conv9x9_kernel,
                         cudaFuncAttributeMaxDynamicSharedMemorySize,
                         SMEM_BYTES);
    conv9x9_kernel<<<32768, 128, SMEM_BYTES>>>(X, (float*)d_out);
}